// round 16
// baseline (speedup 1.0000x reference)
#include <cuda_runtime.h>

#define NBATCH 16
#define PPIX   (640*640)      // 409600 pixels per image
#define NCHUNK (PPIX/4)       // 102400 4-pixel chunks per image

// ---------------- device-global scratch (no allocations allowed) -------------
__device__ float g_sum[NBATCH][8][4];   // kernel-region emb sums per label
__device__ float g_ck [NBATCH][8];      // kernel-region counts per label
__device__ float g_ci [NBATCH][8];      // instance-region counts per label

__device__ __forceinline__ float wredf(float v) {
#pragma unroll
    for (int o = 16; o; o >>= 1) v += __shfl_xor_sync(0xffffffffu, v, o);
    return v;
}

__device__ __forceinline__ float fsqrt_ap(float x) {
    float r;
    asm("sqrt.approx.f32 %0, %1;" : "=f"(r) : "f"(x));
    return r;
}

// predicated packed-f32x2 accumulate: if (lak==l) { slo+=elo; shi+=ehi; }
__device__ __forceinline__ void acc_label(unsigned long long& slo, unsigned long long& shi,
                                          unsigned long long elo, unsigned long long ehi,
                                          int lak, int l) {
    asm("{\n\t.reg .pred p;\n\t"
        "setp.eq.s32 p, %2, %3;\n\t"
        "@p add.rn.f32x2 %0, %0, %4;\n\t"
        "@p add.rn.f32x2 %1, %1, %5;\n\t}"
        : "+l"(slo), "+l"(shi)
        : "r"(lak), "r"(l), "l"(elo), "l"(ehi));
}

__device__ __forceinline__ float u64_lo_f(unsigned long long v) {
    return __uint_as_float((unsigned)(v & 0xffffffffull));
}
__device__ __forceinline__ float u64_hi_f(unsigned long long v) {
    return __uint_as_float((unsigned)(v >> 32));
}

// ---------------- kernel 0: zero accumulators + output -----------------------
__global__ void k_zero(float* out) {
    int t = threadIdx.x;
    if (t < 512) (&g_sum[0][0][0])[t] = 0.f;
    if (t < 128) {
        (&g_ck[0][0])[t] = 0.f;
        (&g_ci[0][0])[t] = 0.f;
    }
    if (t == 0) out[0] = 0.f;
}

// ---------------- pass 1: proven R4 kernel; ker via __ldcs (single-use) ------
#define PASS1_PX(LAB, KV, TV, ELO, EHI)                                   \
    {                                                                     \
        int la  = ((TV) > 0.5f) ? ((LAB) & 7) : 0;                        \
        int lak = ((KV) > 0.5f) ? la : 0;                                 \
        ci64 += 1ull << (8 * la);                                         \
        ck64 += 1ull << (8 * lak);                                        \
        _Pragma("unroll")                                                 \
        for (int l = 1; l < 8; l++)                                       \
            acc_label(s[l-1][0], s[l-1][1], (ELO), (EHI), lak, l);        \
    }

__global__ __launch_bounds__(256)
void k_pass1(const ulonglong2* __restrict__ emb, const int4* __restrict__ inst,
             const float4* __restrict__ ker, const float4* __restrict__ tmk) {
    const int b = blockIdx.y;
    unsigned long long s[7][2];
#pragma unroll
    for (int l = 0; l < 7; l++) { s[l][0] = 0ull; s[l][1] = 0ull; }
    unsigned long long ck64 = 0ull, ci64 = 0ull;

    const size_t base   = (size_t)b * NCHUNK;
    const int    stride = gridDim.x * blockDim.x;
    const int    iters  = NCHUNK / stride;          // floor; >=1
    const int    rem    = NCHUNK - iters * stride;
    const int    t      = blockIdx.x * blockDim.x + threadIdx.x;

    // remainder chunk first (guarded) -> main loop stays uniform
    if (t < rem) {
        const int mr = iters * stride + t;
        int4   iv = inst[base + mr];
        float4 kv = __ldcs(&ker[base + mr]);
        float4 tv = tmk [base + mr];
        const ulonglong2* ep = emb + ((base + (size_t)mr) << 1);
        ulonglong2 ea = ep[0], eb = ep[1], ec = ep[2], ed = ep[3];
        PASS1_PX(iv.x, kv.x, tv.x, ea.x, ea.y);
        PASS1_PX(iv.y, kv.y, tv.y, eb.x, eb.y);
        PASS1_PX(iv.z, kv.z, tv.z, ec.x, ec.y);
        PASS1_PX(iv.w, kv.w, tv.w, ed.x, ed.y);
    }

    int m = t;
    int4   iv = inst[base + m];
    float4 kv = __ldcs(&ker[base + m]);
    float4 tv = tmk [base + m];
    const ulonglong2* ep = emb + ((base + (size_t)m) << 1);
    ulonglong2 ea = ep[0], eb = ep[1], ec = ep[2], ed = ep[3];

    for (int it = 1; it < iters; it++) {
        const int mn = m + stride;
        int4   ivn = inst[base + mn];
        float4 kvn = __ldcs(&ker[base + mn]);
        float4 tvn = tmk [base + mn];
        const ulonglong2* en = emb + ((base + (size_t)mn) << 1);
        ulonglong2 na = en[0], nb = en[1], nc = en[2], nd = en[3];

        PASS1_PX(iv.x, kv.x, tv.x, ea.x, ea.y);
        PASS1_PX(iv.y, kv.y, tv.y, eb.x, eb.y);
        PASS1_PX(iv.z, kv.z, tv.z, ec.x, ec.y);
        PASS1_PX(iv.w, kv.w, tv.w, ed.x, ed.y);

        iv = ivn; kv = kvn; tv = tvn;
        ea = na; eb = nb; ec = nc; ed = nd;
        m = mn;
    }
    PASS1_PX(iv.x, kv.x, tv.x, ea.x, ea.y);
    PASS1_PX(iv.y, kv.y, tv.y, eb.x, eb.y);
    PASS1_PX(iv.z, kv.z, tv.z, ec.x, ec.y);
    PASS1_PX(iv.w, kv.w, tv.w, ed.x, ed.y);

    const unsigned lane = threadIdx.x & 31u;
#pragma unroll
    for (int l = 0; l < 7; l++) {
        float v0 = wredf(u64_lo_f(s[l][0]));
        float v1 = wredf(u64_hi_f(s[l][0]));
        float v2 = wredf(u64_lo_f(s[l][1]));
        float v3 = wredf(u64_hi_f(s[l][1]));
        if (lane == 0) {
            atomicAdd(&g_sum[b][l+1][0], v0);
            atomicAdd(&g_sum[b][l+1][1], v1);
            atomicAdd(&g_sum[b][l+1][2], v2);
            atomicAdd(&g_sum[b][l+1][3], v3);
        }
    }
#pragma unroll
    for (int l = 1; l < 8; l++) {
        float v = wredf((float)((ck64 >> (8*l)) & 255ull));
        if (lane == 0) atomicAdd(&g_ck[b][l], v);
    }
#pragma unroll
    for (int l = 2; l < 8; l++) {
        float v = wredf((float)((ci64 >> (8*l)) & 255ull));
        if (lane == 0) atomicAdd(&g_ci[b][l], v);
    }
}

// ---------------- pass 2: prologue (mu/dis/reg) + agg; writes out directly ---
#define PASS2_PX(LAB, TV, EV, ACC)                                        \
    {                                                                     \
        int la = ((TV) > 0.5f) ? ((LAB) & 7) : 0;                         \
        float4 mm = smu[la];                                              \
        float  w  = swt[la];                                              \
        float dx = (EV).x - mm.x, dy = (EV).y - mm.y;                     \
        float dz = (EV).z - mm.z, dw = (EV).w - mm.w;                     \
        float sq = fmaf(dx, dx, fmaf(dy, dy, fmaf(dz, dz, dw*dw)));      \
        float d  = fsqrt_ap(sq);                                          \
        float x  = fmaxf(d - 0.5f, 0.f);                                  \
        ACC = fmaf(__logf(fmaf(x, x, 1.f)), w, ACC);                      \
    }

__global__ __launch_bounds__(256)
void k_pass2(const float4* __restrict__ emb, const int4* __restrict__ inst,
             const float4* __restrict__ tmk, float* __restrict__ out) {
    const int b = blockIdx.y;
    __shared__ float4 smu[8];
    __shared__ float  swt[8];

    // mu + weights from finalized partials (stream ordering after pass1)
    if (threadIdx.x < 8) {
        int l = threadIdx.x;
        float4 mu = make_float4(0.f, 0.f, 0.f, 0.f);
        float  w  = 0.f;
        if (l > 0) {
            float c = fmaxf(g_ck[b][l], 1.f);
            mu.x = g_sum[b][l][0] / c;
            mu.y = g_sum[b][l][1] / c;
            mu.z = g_sum[b][l][2] / c;
            mu.w = g_sum[b][l][3] / c;
        }
        if (l >= 2) w = 1.0f / (96.0f * fmaxf(g_ci[b][l], 1.f));
        smu[l] = mu;
        swt[l] = w;
    }
    __syncthreads();

    // discrimination + regularization terms (once per batch)
    if (blockIdx.x == 0 && threadIdx.x == 0) {
        float dis = 0.f;
        for (int i = 1; i < 8; i++) {
            float4 a = smu[i];
            for (int j = 1; j < 8; j++) {
                if (j == i) continue;
                float4 c = smu[j];
                float dx = a.x - c.x, dy = a.y - c.y, dz = a.z - c.z, dw = a.w - c.w;
                float dd = sqrtf(dx*dx + dy*dy + dz*dz + dw*dw);
                float x  = fmaxf(3.0f - dd, 0.f);   // 2*DELTA_D - dd
                dis += logf(fmaf(x, x, 1.f));
            }
        }
        dis *= (1.0f / 42.0f);
        float reg = 0.f;
        for (int l = 0; l < 8; l++) {
            float4 a = smu[l];
            float n = sqrtf(a.x*a.x + a.y*a.y + a.z*a.z + a.w*a.w);
            reg += logf(n + 1.f);
        }
        reg *= (0.001f / 8.0f);
        atomicAdd(out, (dis + reg) * (1.0f / 16.0f));
    }

    const size_t base   = (size_t)b * NCHUNK;
    const int    stride = gridDim.x * blockDim.x;
    const int    iters  = NCHUNK / stride;          // floor; >=1
    const int    rem    = NCHUNK - iters * stride;
    const int    t      = blockIdx.x * blockDim.x + threadIdx.x;

    float acc0 = 0.f, acc1 = 0.f;

    // remainder = the rem lowest-indexed chunks (main loop covers the top part)
    if (t < rem) {
        const int mr = t;
        int4   iv = inst[base + mr];
        float4 tv = tmk [base + mr];
        const float4* ep = emb + ((base + (size_t)mr) << 2);
        float4 e0 = ep[0], e1 = ep[1], e2 = ep[2], e3 = ep[3];
        PASS2_PX(iv.x, tv.x, e0, acc0);
        PASS2_PX(iv.y, tv.y, e1, acc1);
        PASS2_PX(iv.z, tv.z, e2, acc0);
        PASS2_PX(iv.w, tv.w, e3, acc1);
    }

    // reversed traversal: first iterations hit pass1's L2-resident tail
    int m = (NCHUNK - 1) - t;
    int4   iv = inst[base + m];
    float4 tv = tmk [base + m];
    const float4* ep = emb + ((base + (size_t)m) << 2);
    float4 e0 = ep[0], e1 = ep[1], e2 = ep[2], e3 = ep[3];

    for (int it = 1; it < iters; it++) {
        const int mn = m - stride;
        int4   ivn = inst[base + mn];
        float4 tvn = tmk [base + mn];
        const float4* en = emb + ((base + (size_t)mn) << 2);
        float4 n0 = en[0], n1 = en[1], n2 = en[2], n3 = en[3];

        PASS2_PX(iv.x, tv.x, e0, acc0);
        PASS2_PX(iv.y, tv.y, e1, acc1);
        PASS2_PX(iv.z, tv.z, e2, acc0);
        PASS2_PX(iv.w, tv.w, e3, acc1);

        iv = ivn; tv = tvn;
        e0 = n0; e1 = n1; e2 = n2; e3 = n3;
        m = mn;
    }
    PASS2_PX(iv.x, tv.x, e0, acc0);
    PASS2_PX(iv.y, tv.y, e1, acc1);
    PASS2_PX(iv.z, tv.z, e2, acc0);
    PASS2_PX(iv.w, tv.w, e3, acc1);

    float v = wredf(acc0 + acc1);
    if ((threadIdx.x & 31u) == 0) atomicAdd(out, v);
}

// ---------------- launch (proven grid policy) --------------------------------
static int pick_gx(int occ, int nsm) {
    if (occ < 1) occ = 1;
    long gx = ((long)occ * nsm) / NBATCH;   // exactly one occupancy wave
    if (gx < 8)   gx = 8;                   // count-field overflow guard
    if (gx > 400) gx = 400;                 // stride <= NCHUNK (iters >= 1)
    return (int)gx;
}

extern "C" void kernel_launch(void* const* d_in, const int* in_sizes, int n_in,
                              void* d_out, int out_size) {
    (void)in_sizes; (void)n_in; (void)out_size;
    const float4* emb  = (const float4*)d_in[0];
    const int4*   inst = (const int4*)  d_in[1];
    const float4* ker  = (const float4*)d_in[2];
    const float4* tmk  = (const float4*)d_in[3];
    float*        out  = (float*)d_out;

    int nsm = 152;
    cudaDeviceGetAttribute(&nsm, cudaDevAttrMultiProcessorCount, 0);
    int occ1 = 0, occ2 = 0;
    cudaOccupancyMaxActiveBlocksPerMultiprocessor(&occ1, k_pass1, 256, 0);
    cudaOccupancyMaxActiveBlocksPerMultiprocessor(&occ2, k_pass2, 256, 0);
    int gx1 = pick_gx(occ1, nsm);
    int gx2 = pick_gx(occ2, nsm);

    k_zero<<<1, 512>>>(out);
    k_pass1<<<dim3(gx1, NBATCH), 256>>>((const ulonglong2*)emb, inst, ker, tmk);
    k_pass2<<<dim3(gx2, NBATCH), 256>>>(emb, inst, tmk, out);
}

// round 17
// speedup vs baseline: 1.1424x; 1.1424x over previous
#include <cuda_runtime.h>

#define NBATCH 16
#define PPIX   (640*640)      // 409600 pixels per image
#define NCHUNK (PPIX/4)       // 102400 4-pixel chunks per image

// ---------------- device-global scratch (no allocations allowed) -------------
__device__ float g_sum[NBATCH][8][4];   // kernel-region emb sums per label
__device__ float g_ck [NBATCH][8];      // kernel-region counts per label
__device__ float g_ci [NBATCH][8];      // instance-region counts per label

__device__ __forceinline__ float wredf(float v) {
#pragma unroll
    for (int o = 16; o; o >>= 1) v += __shfl_xor_sync(0xffffffffu, v, o);
    return v;
}

__device__ __forceinline__ float fsqrt_ap(float x) {
    float r;
    asm("sqrt.approx.f32 %0, %1;" : "=f"(r) : "f"(x));
    return r;
}

// predicated packed-f32x2 accumulate: if (lak==l) { slo+=elo; shi+=ehi; }
__device__ __forceinline__ void acc_label(unsigned long long& slo, unsigned long long& shi,
                                          unsigned long long elo, unsigned long long ehi,
                                          int lak, int l) {
    asm("{\n\t.reg .pred p;\n\t"
        "setp.eq.s32 p, %2, %3;\n\t"
        "@p add.rn.f32x2 %0, %0, %4;\n\t"
        "@p add.rn.f32x2 %1, %1, %5;\n\t}"
        : "+l"(slo), "+l"(shi)
        : "r"(lak), "r"(l), "l"(elo), "l"(ehi));
}

__device__ __forceinline__ float u64_lo_f(unsigned long long v) {
    return __uint_as_float((unsigned)(v & 0xffffffffull));
}
__device__ __forceinline__ float u64_hi_f(unsigned long long v) {
    return __uint_as_float((unsigned)(v >> 32));
}

// ---------------- kernel 0: zero accumulators + output -----------------------
__global__ void k_zero(float* out) {
    int t = threadIdx.x;
    if (t < 512) (&g_sum[0][0][0])[t] = 0.f;
    if (t < 128) {
        (&g_ck[0][0])[t] = 0.f;
        (&g_ci[0][0])[t] = 0.f;
    }
    if (t == 0) out[0] = 0.f;
}

// ---------------- pass 1: byte-exact R15 kernel (NO __ldcs) ------------------
#define PASS1_PX(LAB, KV, TV, ELO, EHI)                                   \
    {                                                                     \
        int la  = ((TV) > 0.5f) ? ((LAB) & 7) : 0;                        \
        int lak = ((KV) > 0.5f) ? la : 0;                                 \
        ci64 += 1ull << (8 * la);                                         \
        ck64 += 1ull << (8 * lak);                                        \
        _Pragma("unroll")                                                 \
        for (int l = 1; l < 8; l++)                                       \
            acc_label(s[l-1][0], s[l-1][1], (ELO), (EHI), lak, l);        \
    }

__global__ __launch_bounds__(256)
void k_pass1(const ulonglong2* __restrict__ emb, const int4* __restrict__ inst,
             const float4* __restrict__ ker, const float4* __restrict__ tmk) {
    const int b = blockIdx.y;
    unsigned long long s[7][2];
#pragma unroll
    for (int l = 0; l < 7; l++) { s[l][0] = 0ull; s[l][1] = 0ull; }
    unsigned long long ck64 = 0ull, ci64 = 0ull;

    const size_t base   = (size_t)b * NCHUNK;
    const int    stride = gridDim.x * blockDim.x;
    const int    iters  = NCHUNK / stride;          // floor; >=1
    const int    rem    = NCHUNK - iters * stride;
    const int    t      = blockIdx.x * blockDim.x + threadIdx.x;

    // remainder chunk first (guarded) -> main loop stays uniform
    if (t < rem) {
        const int mr = iters * stride + t;
        int4   iv = inst[base + mr];
        float4 kv = ker [base + mr];
        float4 tv = tmk [base + mr];
        const ulonglong2* ep = emb + ((base + (size_t)mr) << 1);
        ulonglong2 ea = ep[0], eb = ep[1], ec = ep[2], ed = ep[3];
        PASS1_PX(iv.x, kv.x, tv.x, ea.x, ea.y);
        PASS1_PX(iv.y, kv.y, tv.y, eb.x, eb.y);
        PASS1_PX(iv.z, kv.z, tv.z, ec.x, ec.y);
        PASS1_PX(iv.w, kv.w, tv.w, ed.x, ed.y);
    }

    int m = t;
    int4   iv = inst[base + m];
    float4 kv = ker [base + m];
    float4 tv = tmk [base + m];
    const ulonglong2* ep = emb + ((base + (size_t)m) << 1);
    ulonglong2 ea = ep[0], eb = ep[1], ec = ep[2], ed = ep[3];

    for (int it = 1; it < iters; it++) {
        const int mn = m + stride;
        int4   ivn = inst[base + mn];
        float4 kvn = ker [base + mn];
        float4 tvn = tmk [base + mn];
        const ulonglong2* en = emb + ((base + (size_t)mn) << 1);
        ulonglong2 na = en[0], nb = en[1], nc = en[2], nd = en[3];

        PASS1_PX(iv.x, kv.x, tv.x, ea.x, ea.y);
        PASS1_PX(iv.y, kv.y, tv.y, eb.x, eb.y);
        PASS1_PX(iv.z, kv.z, tv.z, ec.x, ec.y);
        PASS1_PX(iv.w, kv.w, tv.w, ed.x, ed.y);

        iv = ivn; kv = kvn; tv = tvn;
        ea = na; eb = nb; ec = nc; ed = nd;
        m = mn;
    }
    PASS1_PX(iv.x, kv.x, tv.x, ea.x, ea.y);
    PASS1_PX(iv.y, kv.y, tv.y, eb.x, eb.y);
    PASS1_PX(iv.z, kv.z, tv.z, ec.x, ec.y);
    PASS1_PX(iv.w, kv.w, tv.w, ed.x, ed.y);

    const unsigned lane = threadIdx.x & 31u;
#pragma unroll
    for (int l = 0; l < 7; l++) {
        float v0 = wredf(u64_lo_f(s[l][0]));
        float v1 = wredf(u64_hi_f(s[l][0]));
        float v2 = wredf(u64_lo_f(s[l][1]));
        float v3 = wredf(u64_hi_f(s[l][1]));
        if (lane == 0) {
            atomicAdd(&g_sum[b][l+1][0], v0);
            atomicAdd(&g_sum[b][l+1][1], v1);
            atomicAdd(&g_sum[b][l+1][2], v2);
            atomicAdd(&g_sum[b][l+1][3], v3);
        }
    }
#pragma unroll
    for (int l = 1; l < 8; l++) {
        float v = wredf((float)((ck64 >> (8*l)) & 255ull));
        if (lane == 0) atomicAdd(&g_ck[b][l], v);
    }
#pragma unroll
    for (int l = 2; l < 8; l++) {
        float v = wredf((float)((ci64 >> (8*l)) & 255ull));
        if (lane == 0) atomicAdd(&g_ci[b][l], v);
    }
}

// ---------------- pass 2: prologue + agg; block-reduced single atomic to out -
#define PASS2_PX(LAB, TV, EV, ACC)                                        \
    {                                                                     \
        int la = ((TV) > 0.5f) ? ((LAB) & 7) : 0;                         \
        float4 mm = smu[la];                                              \
        float  w  = swt[la];                                              \
        float dx = (EV).x - mm.x, dy = (EV).y - mm.y;                     \
        float dz = (EV).z - mm.z, dw = (EV).w - mm.w;                     \
        float sq = fmaf(dx, dx, fmaf(dy, dy, fmaf(dz, dz, dw*dw)));      \
        float d  = fsqrt_ap(sq);                                          \
        float x  = fmaxf(d - 0.5f, 0.f);                                  \
        ACC = fmaf(__logf(fmaf(x, x, 1.f)), w, ACC);                      \
    }

__global__ __launch_bounds__(256)
void k_pass2(const float4* __restrict__ emb, const int4* __restrict__ inst,
             const float4* __restrict__ tmk, float* __restrict__ out) {
    const int b = blockIdx.y;
    __shared__ float4 smu[8];
    __shared__ float  swt[8];
    __shared__ float  wsum[8];

    // mu + weights from finalized partials (stream ordering after pass1)
    if (threadIdx.x < 8) {
        int l = threadIdx.x;
        float4 mu = make_float4(0.f, 0.f, 0.f, 0.f);
        float  w  = 0.f;
        if (l > 0) {
            float c = fmaxf(g_ck[b][l], 1.f);
            mu.x = g_sum[b][l][0] / c;
            mu.y = g_sum[b][l][1] / c;
            mu.z = g_sum[b][l][2] / c;
            mu.w = g_sum[b][l][3] / c;
        }
        if (l >= 2) w = 1.0f / (96.0f * fmaxf(g_ci[b][l], 1.f));
        smu[l] = mu;
        swt[l] = w;
    }
    __syncthreads();

    // discrimination + regularization terms (once per batch)
    if (blockIdx.x == 0 && threadIdx.x == 0) {
        float dis = 0.f;
        for (int i = 1; i < 8; i++) {
            float4 a = smu[i];
            for (int j = 1; j < 8; j++) {
                if (j == i) continue;
                float4 c = smu[j];
                float dx = a.x - c.x, dy = a.y - c.y, dz = a.z - c.z, dw = a.w - c.w;
                float dd = sqrtf(dx*dx + dy*dy + dz*dz + dw*dw);
                float x  = fmaxf(3.0f - dd, 0.f);   // 2*DELTA_D - dd
                dis += logf(fmaf(x, x, 1.f));
            }
        }
        dis *= (1.0f / 42.0f);
        float reg = 0.f;
        for (int l = 0; l < 8; l++) {
            float4 a = smu[l];
            float n = sqrtf(a.x*a.x + a.y*a.y + a.z*a.z + a.w*a.w);
            reg += logf(n + 1.f);
        }
        reg *= (0.001f / 8.0f);
        atomicAdd(out, (dis + reg) * (1.0f / 16.0f));
    }

    const size_t base   = (size_t)b * NCHUNK;
    const int    stride = gridDim.x * blockDim.x;
    const int    iters  = NCHUNK / stride;          // floor; >=1
    const int    rem    = NCHUNK - iters * stride;
    const int    t      = blockIdx.x * blockDim.x + threadIdx.x;

    float acc0 = 0.f, acc1 = 0.f;

    // remainder = the rem lowest-indexed chunks (main loop covers the top part)
    if (t < rem) {
        const int mr = t;
        int4   iv = inst[base + mr];
        float4 tv = tmk [base + mr];
        const float4* ep = emb + ((base + (size_t)mr) << 2);
        float4 e0 = ep[0], e1 = ep[1], e2 = ep[2], e3 = ep[3];
        PASS2_PX(iv.x, tv.x, e0, acc0);
        PASS2_PX(iv.y, tv.y, e1, acc1);
        PASS2_PX(iv.z, tv.z, e2, acc0);
        PASS2_PX(iv.w, tv.w, e3, acc1);
    }

    // reversed traversal: first iterations hit pass1's L2-resident tail
    int m = (NCHUNK - 1) - t;
    int4   iv = inst[base + m];
    float4 tv = tmk [base + m];
    const float4* ep = emb + ((base + (size_t)m) << 2);
    float4 e0 = ep[0], e1 = ep[1], e2 = ep[2], e3 = ep[3];

    for (int it = 1; it < iters; it++) {
        const int mn = m - stride;
        int4   ivn = inst[base + mn];
        float4 tvn = tmk [base + mn];
        const float4* en = emb + ((base + (size_t)mn) << 2);
        float4 n0 = en[0], n1 = en[1], n2 = en[2], n3 = en[3];

        PASS2_PX(iv.x, tv.x, e0, acc0);
        PASS2_PX(iv.y, tv.y, e1, acc1);
        PASS2_PX(iv.z, tv.z, e2, acc0);
        PASS2_PX(iv.w, tv.w, e3, acc1);

        iv = ivn; tv = tvn;
        e0 = n0; e1 = n1; e2 = n2; e3 = n3;
        m = mn;
    }
    PASS2_PX(iv.x, tv.x, e0, acc0);
    PASS2_PX(iv.y, tv.y, e1, acc1);
    PASS2_PX(iv.z, tv.z, e2, acc0);
    PASS2_PX(iv.w, tv.w, e3, acc1);

    // block-level reduction: 8 warp partials -> one atomic per block
    float v = wredf(acc0 + acc1);
    const int wid = threadIdx.x >> 5;
    if ((threadIdx.x & 31u) == 0) wsum[wid] = v;
    __syncthreads();
    if (threadIdx.x == 0) {
        float bs = wsum[0] + wsum[1] + wsum[2] + wsum[3]
                 + wsum[4] + wsum[5] + wsum[6] + wsum[7];
        atomicAdd(out, bs);
    }
}

// ---------------- launch (proven grid policy) --------------------------------
static int pick_gx(int occ, int nsm) {
    if (occ < 1) occ = 1;
    long gx = ((long)occ * nsm) / NBATCH;   // exactly one occupancy wave
    if (gx < 8)   gx = 8;                   // count-field overflow guard
    if (gx > 400) gx = 400;                 // stride <= NCHUNK (iters >= 1)
    return (int)gx;
}

extern "C" void kernel_launch(void* const* d_in, const int* in_sizes, int n_in,
                              void* d_out, int out_size) {
    (void)in_sizes; (void)n_in; (void)out_size;
    const float4* emb  = (const float4*)d_in[0];
    const int4*   inst = (const int4*)  d_in[1];
    const float4* ker  = (const float4*)d_in[2];
    const float4* tmk  = (const float4*)d_in[3];
    float*        out  = (float*)d_out;

    int nsm = 152;
    cudaDeviceGetAttribute(&nsm, cudaDevAttrMultiProcessorCount, 0);
    int occ1 = 0, occ2 = 0;
    cudaOccupancyMaxActiveBlocksPerMultiprocessor(&occ1, k_pass1, 256, 0);
    cudaOccupancyMaxActiveBlocksPerMultiprocessor(&occ2, k_pass2, 256, 0);
    int gx1 = pick_gx(occ1, nsm);
    int gx2 = pick_gx(occ2, nsm);

    k_zero<<<1, 512>>>(out);
    k_pass1<<<dim3(gx1, NBATCH), 256>>>((const ulonglong2*)emb, inst, ker, tmk);
    k_pass2<<<dim3(gx2, NBATCH), 256>>>(emb, inst, tmk, out);
}